// round 12
// baseline (speedup 1.0000x reference)
#include <cuda_runtime.h>
#include <stdint.h>

// B = 1048576, D = 3, L = 16, C = 2, H = 16, S = 1.0
//   res(l) = 16 << l, side = res+1; dense l=0,1,2; hashed l>=3 (hm = 2^19)
//   offsets: 0, 4920, 40864, 315496, then +524288/level (all even)
//   table = concat(ext[524288,2], own[.,2])
//
// R12: two kernels, level-class uniform warps.
//   Hashed kernel: thread = (point b, j=l-3), all lanes hashed -> one load
//     arm, no dense-arm issue duplication (~16 vs 24 mem instr per warp).
//   Dense kernel: thread = point, all 3 dense levels; tables (39KB/287KB/
//     2.2MB, all in ext) are L1/L2 hot; unpolluted by hashed streams.

#define HASH_SPLIT 524288u
#define P2 2654435761u
#define P3 805459861u
#define B_PTS 1048576u

// ---------------- hashed levels (l = 3..15) ----------------
__global__ void __launch_bounds__(256)
grid_encode_hashed(const float* __restrict__ pts,
                   const float2* __restrict__ ext,
                   const float2* __restrict__ own,
                   float2* __restrict__ out)
{
    const unsigned gtid = blockIdx.x * 256u + threadIdx.x;   // < B*13
    const unsigned b = gtid / 13u;
    const unsigned j = gtid - b * 13u;      // level = j + 3

    const float px_in = __ldg(&pts[3u * b + 0u]);
    const float py_in = __ldg(&pts[3u * b + 1u]);
    const float pz_in = __ldg(&pts[3u * b + 2u]);

    const unsigned res = 128u << j;         // 16 << (j+3)
    const float scale  = (float)(res - 1u);

    // pos >= 0.5 always: truncation == floor.
    const float posx = (px_in + 1.0f) * 0.5f * scale + 0.5f;
    const float posy = (py_in + 1.0f) * 0.5f * scale + 0.5f;
    const float posz = (pz_in + 1.0f) * 0.5f * scale + 0.5f;

    const unsigned x0 = (unsigned)posx;
    const unsigned y0 = (unsigned)posy;
    const unsigned z0 = (unsigned)posz;
    const float fx = posx - (float)x0;
    const float fy = posy - (float)y0;
    const float fz = posz - (float)z0;

    const unsigned off = 315496u + j * 524288u;
    // ext/own threshold: idx < T -> ext+g, else own+(g-HASH_SPLIT).
    // Only j==0 (level 3) straddles the boundary; j>=1 is always own.
    const unsigned T = (j == 0u) ? HASH_SPLIT : 0u;
    const float2* __restrict__ ownm = own - HASH_SPLIT;

    // Hash per-axis terms (uint32 wraparound; PRIMES = {1, P2, P3}).
    const unsigned hy0 = y0 * P2;
    const unsigned hz0 = z0 * P3;
    const unsigned hys[2] = { hy0, hy0 + P2 };
    const unsigned hzs[2] = { hz0, hz0 + P3 };

    unsigned ia[4], ib[4];
#pragma unroll
    for (int p = 0; p < 4; ++p) {
        const int cy = p & 1, cz = (p >> 1) & 1;
        const unsigned hb = hys[cy] ^ hzs[cz];
        ia[p] = off + ((x0 ^ hb) & (HASH_SPLIT - 1u));
        ib[p] = off + (((x0 + 1u) ^ hb) & (HASH_SPLIT - 1u));
    }

    // Pair-merged fetch: one aligned LDG.128 when (a^b)==1 (x0 even, since
    // PRIMES[0]==1), else two LDG.64. Pairs never cross level/half
    // boundaries (all even).
    float2 v0[4], v1[4];
#pragma unroll
    for (int p = 0; p < 4; ++p) {
        const unsigned a = ia[p], bb = ib[p];
        if ((a ^ bb) == 1u) {
            const unsigned lo = a & ~1u;
            const float2* q = (lo < T) ? (ext + lo) : (ownm + lo);
            const float4 w4 = __ldg((const float4*)q);
            const bool swap = (a & 1u);
            v0[p] = swap ? make_float2(w4.z, w4.w) : make_float2(w4.x, w4.y);
            v1[p] = swap ? make_float2(w4.x, w4.y) : make_float2(w4.z, w4.w);
        } else {
            const float2* qa = (a  < T) ? (ext + a)  : (ownm + a);
            const float2* qb = (bb < T) ? (ext + bb) : (ownm + bb);
            v0[p] = __ldg(qa);
            v1[p] = __ldg(qb);
        }
    }

    const float wx0 = 1.0f - fx, wx1 = fx;
    const float wy[2] = { 1.0f - fy, fy };
    const float wz[2] = { 1.0f - fz, fz };

    float accx = 0.0f, accy = 0.0f;
#pragma unroll
    for (int p = 0; p < 4; ++p) {
        const int cy = p & 1, cz = (p >> 1) & 1;
        const float w = wy[cy] * wz[cz];
        accx += w * (wx0 * v0[p].x + wx1 * v1[p].x);
        accy += w * (wx0 * v0[p].y + wx1 * v1[p].y);
    }

    out[b * 16u + 3u + j] = make_float2(accx, accy);
}

// ---------------- dense levels (l = 0,1,2), one thread per point ----------
__global__ void __launch_bounds__(256)
grid_encode_dense(const float* __restrict__ pts,
                  const float2* __restrict__ ext,
                  float2* __restrict__ out)
{
    const unsigned b = blockIdx.x * 256u + threadIdx.x;

    const float px_in = __ldg(&pts[3u * b + 0u]);
    const float py_in = __ldg(&pts[3u * b + 1u]);
    const float pz_in = __ldg(&pts[3u * b + 2u]);

    const float x01 = (px_in + 1.0f) * 0.5f;
    const float y01 = (py_in + 1.0f) * 0.5f;
    const float z01 = (pz_in + 1.0f) * 0.5f;

    float2 lv[3];
#pragma unroll
    for (int l = 0; l < 3; ++l) {
        const unsigned res   = 16u << l;
        const float    scale = (float)(res - 1u);
        const unsigned side  = res + 1u;
        const unsigned side2 = side * side;
        const unsigned off   = (l == 0) ? 0u : (l == 1 ? 4920u : 40864u);

        const float posx = x01 * scale + 0.5f;
        const float posy = y01 * scale + 0.5f;
        const float posz = z01 * scale + 0.5f;
        const unsigned x0 = (unsigned)posx;
        const unsigned y0 = (unsigned)posy;
        const unsigned z0 = (unsigned)posz;
        const float fx = posx - (float)x0;
        const float fy = posy - (float)y0;
        const float fz = posz - (float)z0;

        const unsigned base = off + x0 + y0 * side + z0 * side2;
        const unsigned dy[2] = { 0u, side };
        const unsigned dz[2] = { 0u, side2 };

        const float wx0 = 1.0f - fx, wx1 = fx;
        const float wy[2] = { 1.0f - fy, fy };
        const float wz[2] = { 1.0f - fz, fz };

        float accx = 0.0f, accy = 0.0f;
#pragma unroll
        for (int p = 0; p < 4; ++p) {
            const int cy = p & 1, cz = (p >> 1) & 1;
            const unsigned a = base + dy[cy] + dz[cz];   // corner pair a, a+1
            float2 va, vb;
            if ((a & 1u) == 0u) {
                const float4 w4 = __ldg((const float4*)(ext + a));
                va = make_float2(w4.x, w4.y);
                vb = make_float2(w4.z, w4.w);
            } else {
                va = __ldg(ext + a);
                vb = __ldg(ext + a + 1u);
            }
            const float w = wy[cy] * wz[cz];
            accx += w * (wx0 * va.x + wx1 * vb.x);
            accy += w * (wx0 * va.y + wx1 * vb.y);
        }
        lv[l] = make_float2(accx, accy);
    }

    // out + b*16 is 128B-aligned: one STG.128 (levels 0,1) + one STG.64 (2).
    float4* o4 = (float4*)(out + b * 16u);
    *o4 = make_float4(lv[0].x, lv[0].y, lv[1].x, lv[1].y);
    out[b * 16u + 2u] = lv[2];
}

extern "C" void kernel_launch(void* const* d_in, const int* in_sizes, int n_in,
                              void* d_out, int out_size)
{
    const float*  pts = (const float*)d_in[0];        // [B, 3]
    const float2* ext = (const float2*)d_in[1];       // [524288, 2]
    const float2* own = (const float2*)d_in[2];       // [N_TABLE - 524288, 2]
    float2* out = (float2*)d_out;                     // [B*16] float2

    // Hashed: B*13 = 13631488 threads -> 53248 blocks of 256.
    grid_encode_hashed<<<53248, 256>>>(pts, ext, own, out);
    // Dense: B threads -> 4096 blocks of 256.
    grid_encode_dense<<<4096, 256>>>(pts, ext, out);
}

// round 13
// speedup vs baseline: 1.0309x; 1.0309x over previous
#include <cuda_runtime.h>
#include <stdint.h>

// B = 1048576, D = 3, L = 16, C = 2, H = 16, S = 1.0
//   res(l) = 16 << l, side = res+1; dense l=0,1,2; hashed l>=3 (hm = 2^19)
//   offsets: 0, 4920, 40864, 315496, then +524288/level (all even)
//   table = concat(ext[524288,2], own[.,2])
//
// R13 = R10 (best, 289us) + thread-uniform pairing in the hashed arm:
//   pairedness depends only on x0 parity (x0 even -> all 4 pairs are
//   {lo,lo+1}; x0 odd -> never paired, since x0^(x0+1) >= 3). One branch
//   instead of four; even arm skips computing ib entirely.
//   Floor via truncation (pos >= 0.5 always). Plain stores (stcs was neutral).

#define HASH_SPLIT 524288u
#define P2 2654435761u
#define P3 805459861u

__global__ void __launch_bounds__(256)
grid_encode_kernel(const float* __restrict__ pts,
                   const float2* __restrict__ ext,
                   const float2* __restrict__ own,
                   float2* __restrict__ out)
{
    const unsigned gtid = blockIdx.x * 256u + threadIdx.x;
    const unsigned b = gtid >> 4;
    const unsigned l = gtid & 15u;

    const float px_in = __ldg(&pts[3u * b + 0u]);
    const float py_in = __ldg(&pts[3u * b + 1u]);
    const float pz_in = __ldg(&pts[3u * b + 2u]);

    const unsigned res  = 16u << l;
    const float scale   = (float)(res - 1u);
    const unsigned side = res + 1u;

    // pos >= 0.5 always: truncation == floor.
    const float posx = (px_in + 1.0f) * 0.5f * scale + 0.5f;
    const float posy = (py_in + 1.0f) * 0.5f * scale + 0.5f;
    const float posz = (pz_in + 1.0f) * 0.5f * scale + 0.5f;

    const unsigned x0 = (unsigned)posx;
    const unsigned y0 = (unsigned)posy;
    const unsigned z0 = (unsigned)posz;
    const float fx = posx - (float)x0;
    const float fy = posy - (float)y0;
    const float fz = posz - (float)z0;

    const bool hashed = (l >= 3u);
    const unsigned off = hashed ? (315496u + (l - 3u) * 524288u)
                                : (l == 0u ? 0u : (l == 1u ? 4920u : 40864u));

    // ext/own threshold: idx < T -> ext + g ; else own + (g - HASH_SPLIT).
    // l<=2: always ext. l==3: straddles. l>=4: always own.
    const unsigned T = (l < 3u) ? 0xFFFFFFFFu : (l == 3u ? HASH_SPLIT : 0u);
    const float2* __restrict__ ownm = own - HASH_SPLIT;

    const float wx0 = 1.0f - fx, wx1 = fx;
    const float wy[2] = { 1.0f - fy, fy };
    const float wz[2] = { 1.0f - fz, fz };

    float2 v0[4], v1[4];

    if (hashed) {
        // Hash per-axis terms (uint32 wraparound; PRIMES = {1, P2, P3}).
        const unsigned hy0 = y0 * P2;
        const unsigned hz0 = z0 * P3;
        const unsigned hys[2] = { hy0, hy0 + P2 };
        const unsigned hzs[2] = { hz0, hz0 + P3 };

        if ((x0 & 1u) == 0u) {
            // x0 even: every pair occupies one aligned 16B slot {lo, lo+1}.
            // (x0^(x0+1) == 1; mask keeps bit 0.) Corner a's slot half is
            // bit0 of a = (hb & 1). Pairs never cross level/half boundaries
            // (all offsets/sizes even).
#pragma unroll
            for (int p = 0; p < 4; ++p) {
                const int cy = p & 1, cz = (p >> 1) & 1;
                const unsigned hb = hys[cy] ^ hzs[cz];
                const unsigned a  = off + ((x0 ^ hb) & (HASH_SPLIT - 1u));
                const unsigned lo = a & ~1u;
                const float2* q = (lo < T) ? (ext + lo) : (ownm + lo);
                const float4 w4 = __ldg((const float4*)q);
                const bool swap = (a & 1u);
                v0[p] = swap ? make_float2(w4.z, w4.w) : make_float2(w4.x, w4.y);
                v1[p] = swap ? make_float2(w4.x, w4.y) : make_float2(w4.z, w4.w);
            }
        } else {
            // x0 odd: never pairable (x0^(x0+1) >= 3). Two LDG.64 per pair.
#pragma unroll
            for (int p = 0; p < 4; ++p) {
                const int cy = p & 1, cz = (p >> 1) & 1;
                const unsigned hb = hys[cy] ^ hzs[cz];
                const unsigned a  = off + ((x0 ^ hb) & (HASH_SPLIT - 1u));
                const unsigned bb = off + (((x0 + 1u) ^ hb) & (HASH_SPLIT - 1u));
                const float2* qa = (a  < T) ? (ext + a)  : (ownm + a);
                const float2* qb = (bb < T) ? (ext + bb) : (ownm + bb);
                v0[p] = __ldg(qa);
                v1[p] = __ldg(qb);
            }
        }
    } else {
        // Dense levels: all inside ext; corners consecutive (b = a+1);
        // parity alternates with cy/cz (side odd), so keep per-pair branch.
        const unsigned side2 = side * side;
        const unsigned dys[2] = { y0 * side,  y0 * side + side };
        const unsigned dzs[2] = { z0 * side2, z0 * side2 + side2 };
#pragma unroll
        for (int p = 0; p < 4; ++p) {
            const int cy = p & 1, cz = (p >> 1) & 1;
            const unsigned a = off + x0 + dys[cy] + dzs[cz];
            if ((a & 1u) == 0u) {
                const float4 w4 = __ldg((const float4*)(ext + a));
                v0[p] = make_float2(w4.x, w4.y);
                v1[p] = make_float2(w4.z, w4.w);
            } else {
                v0[p] = __ldg(ext + a);
                v1[p] = __ldg(ext + a + 1u);
            }
        }
    }

    float accx = 0.0f, accy = 0.0f;
#pragma unroll
    for (int p = 0; p < 4; ++p) {
        const int cy = p & 1, cz = (p >> 1) & 1;
        const float w = wy[cy] * wz[cz];
        accx += w * (wx0 * v0[p].x + wx1 * v1[p].x);
        accy += w * (wx0 * v0[p].y + wx1 * v1[p].y);
    }

    out[gtid] = make_float2(accx, accy);
}

extern "C" void kernel_launch(void* const* d_in, const int* in_sizes, int n_in,
                              void* d_out, int out_size)
{
    const float*  pts = (const float*)d_in[0];        // [B, 3]
    const float2* ext = (const float2*)d_in[1];       // [524288, 2]
    const float2* own = (const float2*)d_in[2];       // [N_TABLE - 524288, 2]
    float2* out = (float2*)d_out;                     // [B*16] float2

    grid_encode_kernel<<<65536, 256>>>(pts, ext, own, out);
}